// round 10
// baseline (speedup 1.0000x reference)
#include <cuda_runtime.h>

// fields: (B=64, H=512, W=512, C=6) float32
// pump_indices: (B, 2) int32
// out: (B, H, W, 4) float32 — per-sample mean of the 5x5 window over channels
//                             [2:6], broadcast over the whole (H, W) plane.
//
// Fused, barrier-free kernel. Geometry: constant warp count (65536),
// finest block quantum yet:
//   grid = (512, 64) = 32768 blocks x 64 thr, 8 KB of stores per block.
//   32 CTAs/SM x 64 thr = 2048 resident threads/SM (same as R9).
//   Every warp redundantly computes its sample's 25-pixel window mean
//   (no smem / no __syncthreads), then streams coalesced float4 stores.

#define H_DIM 512
#define W_DIM 512
#define C_DIM 6
#define RADIUS 2
#define WIN 5              // 2*RADIUS+1
#define WIN_PIX (WIN*WIN)  // 25
#define HW (H_DIM * W_DIM) // 262144 pixels per sample

#define FILL_THREADS 64
#define FILL_ITERS 8       // 64 thr * 8 * 16 B = 8 KB per block
// grid.x = HW / (FILL_THREADS * FILL_ITERS) = 512

__global__ void __launch_bounds__(FILL_THREADS)
fused_64t_kernel(const float* __restrict__ fields,
                 const int* __restrict__ pump_indices,
                 float4* __restrict__ out) {
    const int b = blockIdx.y;
    const int lane = threadIdx.x & 31;

    // ---- every warp: redundant window-mean computation (no barriers) ----
    // Single 64-bit load for (py, px).
    const int2 pidx = __ldg(reinterpret_cast<const int2*>(pump_indices) + b);
    const int py = pidx.x;
    const int px = pidx.y;

    float s0 = 0.f, s1 = 0.f, s2 = 0.f, s3 = 0.f;
    if (lane < WIN_PIX) {
        const int dy = lane / WIN;
        const int dx = lane % WIN;
        const int y = py - RADIUS + dy;
        const int x = px - RADIUS + dx;
        // channel offset 2 within a 6-float pixel -> 8-byte aligned
        const float* p = fields
            + ((size_t)b * HW + (size_t)y * W_DIM + x) * C_DIM + 2;
        float2 a = __ldg(reinterpret_cast<const float2*>(p));
        float2 c = __ldg(reinterpret_cast<const float2*>(p + 2));
        s0 = a.x; s1 = a.y; s2 = c.x; s3 = c.y;
    }

    // Butterfly reduce: all 32 lanes end with the full sum.
    #pragma unroll
    for (int off = 16; off > 0; off >>= 1) {
        s0 += __shfl_xor_sync(0xFFFFFFFFu, s0, off);
        s1 += __shfl_xor_sync(0xFFFFFFFFu, s1, off);
        s2 += __shfl_xor_sync(0xFFFFFFFFu, s2, off);
        s3 += __shfl_xor_sync(0xFFFFFFFFu, s3, off);
    }

    const float inv = 1.0f / (float)WIN_PIX;
    const float4 m = make_float4(s0 * inv, s1 * inv, s2 * inv, s3 * inv);

    // ---- coalesced float4 store stream: 8 KB per block ----
    float4* dst = out + (size_t)b * HW
                      + (size_t)blockIdx.x * (FILL_THREADS * FILL_ITERS)
                      + threadIdx.x;
    #pragma unroll
    for (int i = 0; i < FILL_ITERS; ++i) {
        dst[i * FILL_THREADS] = m;
    }
}

extern "C" void kernel_launch(void* const* d_in, const int* in_sizes, int n_in,
                              void* d_out, int out_size) {
    const float* fields = (const float*)d_in[0];
    const int* pump_indices = (const int*)d_in[1];
    float4* out = (float4*)d_out;

    const int B = in_sizes[1] / 2;  // (B, 2) int32

    dim3 grid(HW / (FILL_THREADS * FILL_ITERS), B);
    fused_64t_kernel<<<grid, FILL_THREADS>>>(fields, pump_indices, out);
}